// round 8
// baseline (speedup 1.0000x reference)
#include <cuda_runtime.h>
#include <cuda_bf16.h>
#include <cstdint>

// Problem constants: B=8, S=2048, D=1024, F=64, TOPK=8
#define Dd     1024
#define Ff     64
#define FO     192              // 3*F fused outputs (top | feat | gates)
#define TMX    112              // max tokens per CTA (7 m16 tiles)
#define KC     64               // K chunk (elements)
#define NCH    (Dd / KC)        // 16
#define TOKENS 16384
#define NCTA   148              // 136 x 112 tokens + 12 x 96 tokens
#define NT     512

#define PIT     144             // bf16 smem row pitch bytes
#define ALOOF   (TMX * PIT)         // 16128 (lo offset within an Abf buffer)
#define ABF_BUF (2 * TMX * PIT)     // 32256
#define A32PIT  272                 // fp32 staging row pitch (16B-aligned)
#define S_A32   0                   // 112*272 = 30464 (single buffer)
#define S_ABF   30464               // 2 buffers x 32256
#define S_B     (S_ABF + 2 * ABF_BUF)   // 94976
#define B_BUF   (2 * FO * PIT)          // 55296
#define B_LO    (FO * PIT)              // 27648
#define SMEMSZ  (S_B + 2 * B_BUF)       // 205568
#define EPIP    194                 // epilogue row pitch (floats)

// Repacked weights, bf16 hi/lo split, n-major [FO][Dd]
__device__ __nv_bfloat16 g_Whi[FO * Dd];
__device__ __nv_bfloat16 g_Wlo[FO * Dd];

__device__ __forceinline__ void mma16816(float* c, const uint32_t* a,
                                         uint32_t b0, uint32_t b1) {
    asm("mma.sync.aligned.m16n8k16.row.col.f32.bf16.bf16.f32 "
        "{%0,%1,%2,%3}, {%4,%5,%6,%7}, {%8,%9}, {%0,%1,%2,%3};"
        : "+f"(c[0]), "+f"(c[1]), "+f"(c[2]), "+f"(c[3])
        : "r"(a[0]), "r"(a[1]), "r"(a[2]), "r"(a[3]), "r"(b0), "r"(b1));
}
#define LDSM4(R, addr)                                                        \
    asm volatile("ldmatrix.sync.aligned.m8n8.x4.shared.b16 {%0,%1,%2,%3}, [%4];" \
                 : "=r"((R)[0]), "=r"((R)[1]), "=r"((R)[2]), "=r"((R)[3])     \
                 : "r"(addr))

__device__ __forceinline__ uint32_t s2u(const void* p) {
    uint32_t a;
    asm("{ .reg .u64 t; cvta.to.shared.u64 t, %1; cvt.u32.u64 %0, t; }"
        : "=r"(a) : "l"(p));
    return a;
}
// Split a pair of fp32 into bf16x2 hi and bf16x2 lo (residual).
__device__ __forceinline__ void split2(float2 f, uint32_t& hi, uint32_t& lo) {
    __nv_bfloat162 h2 = __float22bfloat162_rn(f);        // low = f.x, high = f.y
    uint32_t h; memcpy(&h, &h2, 4);
    float h0 = __uint_as_float(h << 16);
    float h1 = __uint_as_float(h & 0xFFFF0000u);
    __nv_bfloat162 l2 = __float22bfloat162_rn(make_float2(f.x - h0, f.y - h1));
    memcpy(&lo, &l2, 4);
    hi = h;
}

// Coalesced repack: blocks 0..127 transpose W_top/W_feat; blocks 128..383 copy W_gates.
__global__ __launch_bounds__(256)
void repack_kernel(const float* __restrict__ Wt,
                   const float* __restrict__ Wf,
                   const float* __restrict__ Wg) {
    int b = blockIdx.x;
    if (b < 128) {
        __shared__ float tile[32][33];
        int ntile = b & 3, ktile = b >> 2;
        int tx = threadIdx.x & 31, ty = threadIdx.x >> 5;  // 32 x 8
        int n0 = ntile * 32, k0 = ktile * 32;
        const float* src = (n0 < Ff) ? Wt : Wf;
        int nb = (n0 < Ff) ? n0 : (n0 - Ff);
#pragma unroll
        for (int r = 0; r < 32; r += 8)
            tile[ty + r][tx] = src[(size_t)(k0 + ty + r) * Ff + nb + tx];
        __syncthreads();
#pragma unroll
        for (int r = 0; r < 32; r += 8) {
            float w = tile[tx][ty + r];
            __nv_bfloat16 hi = __float2bfloat16_rn(w);
            float lo = w - __bfloat162float(hi);
            size_t o = (size_t)(n0 + ty + r) * Dd + k0 + tx;
            g_Whi[o] = hi;
            g_Wlo[o] = __float2bfloat16_rn(lo);
        }
    } else {
        int i = (b - 128) * 256 + threadIdx.x;   // Ff*Dd = 65536 elems
        if (i < Ff * Dd) {
            float w = Wg[i];                      // already n-major
            __nv_bfloat16 hi = __float2bfloat16_rn(w);
            float lo = w - __bfloat162float(hi);
            size_t o = (size_t)(2 * Ff) * Dd + i;
            g_Whi[o] = hi;
            g_Wlo[o] = __float2bfloat16_rn(lo);
        }
    }
}

__global__ __launch_bounds__(NT, 1)
void moe_mma_kernel(const float* __restrict__ x,
                    const float* __restrict__ b_top,
                    const float* __restrict__ b_feat,
                    const float* __restrict__ b_gates,
                    const float* __restrict__ alpha,
                    const int*   __restrict__ nump,
                    float* __restrict__ out) {
    extern __shared__ char smc[];

    const int tid  = threadIdx.x;
    const int wid  = tid >> 5;
    const int lane = tid & 31;
    const int cid  = blockIdx.x;
    const uint32_t smemBase = s2u(smc);

    // Work distribution: 136 CTAs x 7 m16-tiles, 12 CTAs x 6 m16-tiles
    const int T    = (cid < 136) ? 7 : 6;
    const int tok0 = (cid < 136) ? cid * 112 : 136 * 112 + (cid - 136) * 96;
    const int Mloc = T * 16;

    // Warp owns: n-slice 24 cols (warp_n 0..7) x m-half (mh 0: tiles 0-3, mh 1: tiles 4..T-1)
    const int warp_n = wid & 7;
    const int mh     = wid >> 3;
    const int mcnt   = mh ? (T - 4) : 4;

    float acc[4][3][4];
#pragma unroll
    for (int i = 0; i < 4; i++)
#pragma unroll
        for (int j = 0; j < 3; j++)
#pragma unroll
            for (int q = 0; q < 4; q++) acc[i][j][q] = 0.0f;

    // ---- cp.async loaders ----
    auto cpA = [&](int kb) {
#pragma unroll
        for (int p = 0; p < 4; p++) {
            int s   = p * NT + tid;         // 0..2047 (1792 used)
            int row = s >> 4, seg = s & 15;
            if (row < Mloc) {
                const float* src = x + (size_t)(tok0 + row) * Dd + kb + seg * 4;
                uint32_t dst = smemBase + S_A32 + row * A32PIT + seg * 16;
                asm volatile("cp.async.cg.shared.global [%0], [%1], 16;"
                             :: "r"(dst), "l"(src));
            }
        }
    };
    auto cpB = [&](int kb, int buf) {
        uint32_t bdst = smemBase + S_B + buf * B_BUF;
#pragma unroll
        for (int p = 0; p < 6; p++) {
            int u   = p * NT + tid;          // 0..3071
            int mat = (u >= 1536);
            int v   = mat ? (u - 1536) : u;  // 192 rows x 8 16B-segs
            int n   = v >> 3, q = v & 7;
            const __nv_bfloat16* src =
                (mat ? g_Wlo : g_Whi) + (size_t)n * Dd + kb + q * 8;
            uint32_t dst = bdst + (mat ? B_LO : 0) + n * PIT + q * 16;
            asm volatile("cp.async.cg.shared.global [%0], [%1], 16;"
                         :: "r"(dst), "l"(src));
        }
    };

    // ---- shared convert: A32 staging -> Abf[buf] bf16 hi/lo (once per chunk) ----
    auto convert = [&](int buf) {
        int row = tid >> 2, q = tid & 3;     // 16 floats per thread
        if (row < Mloc) {
            const char* src = smc + S_A32 + row * A32PIT + q * 64;
            char* dhi = smc + S_ABF + buf * ABF_BUF + row * PIT + q * 32;
            char* dlo = dhi + ALOOF;
#pragma unroll
            for (int j = 0; j < 4; j++) {
                float4 v = *(const float4*)(src + j * 16);
                uint32_t h0, l0, h1, l1;
                split2(make_float2(v.x, v.y), h0, l0);
                split2(make_float2(v.z, v.w), h1, l1);
                *(uint2*)(dhi + j * 8) = make_uint2(h0, h1);
                *(uint2*)(dlo + j * 8) = make_uint2(l0, l1);
            }
        }
    };

    // ---- ldmatrix lane address bases ----
    const int ll = lane & 15;
    const uint32_t bLaneOff = (ll & 7) * PIT + ((ll >> 3) & 1) * 16
                            + (lane >> 4) * B_LO;   // lanes 16-31 -> lo matrix
    const uint32_t bBase0 = smemBase + S_B + (warp_n * 24) * PIT + bLaneOff;
    const uint32_t aLaneOff =
        ((lane & 7) + ((lane >> 3) & 1) * 8) * PIT + (lane >> 4) * 16;
    const uint32_t aBase0 = smemBase + S_ABF + aLaneOff + (mh * 4) * 16 * PIT;

    auto domma = [&](int buf) {
        uint32_t A0 = aBase0 + buf * ABF_BUF;
        uint32_t B0 = bBase0 + buf * B_BUF;
#pragma unroll
        for (int ks = 0; ks < 4; ks++) {
            uint32_t bf[3][4];
#pragma unroll
            for (int j = 0; j < 3; j++)
                LDSM4(bf[j], B0 + j * 8 * PIT + ks * 32);
            uint32_t ah[4][4], al[4][4];
#pragma unroll
            for (int i = 0; i < 4; i++)
                if (i < mcnt) {
                    LDSM4(ah[i], A0 + i * 16 * PIT + ks * 32);
                    LDSM4(al[i], A0 + ALOOF + i * 16 * PIT + ks * 32);
                }
            // term 1: Ah * Bh
#pragma unroll
            for (int i = 0; i < 4; i++)
                if (i < mcnt)
#pragma unroll
                    for (int j = 0; j < 3; j++)
                        mma16816(acc[i][j], ah[i], bf[j][0], bf[j][1]);
            // term 2: Al * Bh
#pragma unroll
            for (int i = 0; i < 4; i++)
                if (i < mcnt)
#pragma unroll
                    for (int j = 0; j < 3; j++)
                        mma16816(acc[i][j], al[i], bf[j][0], bf[j][1]);
            // term 3: Ah * Bl
#pragma unroll
            for (int i = 0; i < 4; i++)
                if (i < mcnt)
#pragma unroll
                    for (int j = 0; j < 3; j++)
                        mma16816(acc[i][j], ah[i], bf[j][2], bf[j][3]);
        }
    };

    // ---- prologue: chunk 0 resident + chunk 1 in flight ----
    cpA(0); cpB(0, 0);
    asm volatile("cp.async.commit_group;");
    asm volatile("cp.async.wait_group 0;" ::: "memory");
    __syncthreads();
    convert(0);
    __syncthreads();
    cpA(KC); cpB(KC, 1);
    asm volatile("cp.async.commit_group;");

    // ---- mainloop ----
    for (int ch = 0; ch < NCH; ch++) {
        const int buf = ch & 1;
        domma(buf);
        if (ch + 1 < NCH) {
            asm volatile("cp.async.wait_group 0;" ::: "memory");
            __syncthreads();                  // A32(ch+1)/B(ch+1) visible to all
            convert(buf ^ 1);
        }
        __syncthreads();                      // converts visible; buffers reusable
        if (ch + 2 < NCH) {
            cpA((ch + 2) * KC); cpB((ch + 2) * KC, buf);
            asm volatile("cp.async.commit_group;");
        }
    }

    // ---- dump accumulators to epilogue smem [TMX][EPIP] ----
    float* epi = (float*)smc;
#pragma unroll
    for (int i = 0; i < 4; i++)
        if (i < mcnt)
#pragma unroll
            for (int j = 0; j < 3; j++) {
                int r = (mh * 4 + i) * 16 + (lane >> 2);
                int c = warp_n * 24 + j * 8 + (lane & 3) * 2;
                *(float2*)(epi + (size_t)r * EPIP + c) =
                    make_float2(acc[i][j][0], acc[i][j][1]);
                *(float2*)(epi + (size_t)(r + 8) * EPIP + c) =
                    make_float2(acc[i][j][2], acc[i][j][3]);
            }
    __syncthreads();

    // ---- per-token epilogue (one thread per token) ----
    if (tid < Mloc) {
        float* r = epi + (size_t)tid * EPIP;

        const float av = alpha[0];
        const float a  = 1.0f / (1.0f + __expf(-av));
        int num = nump ? *nump : 8;
        if (num < 1)  num = 1;
        if (num > Ff) num = Ff;

        for (int f = 0; f < Ff; ++f) {
            r[f]          += b_top[f];
            r[Ff + f]     += b_feat[f];
            float g = r[2 * Ff + f] + b_gates[f];
            r[2 * Ff + f] = 1.0f / (1.0f + __expf(-g));
        }

        // dense branch: softmax(feat) . gates
        float m2 = -3.4e38f;
        for (int f = 0; f < Ff; ++f) m2 = fmaxf(m2, r[Ff + f]);
        float s2 = 0.0f, ds = 0.0f;
        for (int f = 0; f < Ff; ++f) {
            float e = __expf(r[Ff + f] - m2);
            s2 += e;
            ds += e * r[2 * Ff + f];
        }
        float dense = ds / s2;

        // top-k branch: streaming selection + softmax over selected
        float v0 = 0.0f, se = 0.0f, ta = 0.0f;
        for (int t = 0; t < num; ++t) {
            float best = -3.4e38f; int bi = 0;
            for (int f = 0; f < Ff; ++f) {
                float v = r[f];
                if (v > best) { best = v; bi = f; }
            }
            if (t == 0) v0 = best;
            float e = __expf(best - v0);
            se += e;
            ta += e * r[2 * Ff + bi];
            r[bi] = -3.4e38f;
        }
        float topp = ta / se;

        out[tok0 + tid] = a * topp + (1.0f - a) * dense;
    }
}

extern "C" void kernel_launch(void* const* d_in, const int* in_sizes, int n_in,
                              void* d_out, int out_size) {
    const float* x   = (const float*)d_in[0];
    const float* Wt  = (const float*)d_in[1];
    const float* bt  = (const float*)d_in[2];
    const float* Wf  = (const float*)d_in[3];
    const float* bfi = (const float*)d_in[4];
    const float* Wg  = (const float*)d_in[5];
    const float* bg  = (const float*)d_in[6];
    const float* al  = (const float*)d_in[7];
    const int*   nm  = (n_in > 8) ? (const int*)d_in[8] : nullptr;
    float* out = (float*)d_out;

    repack_kernel<<<384, 256>>>(Wt, Wf, Wg);

    cudaFuncSetAttribute(moe_mma_kernel,
                         cudaFuncAttributeMaxDynamicSharedMemorySize, SMEMSZ);
    moe_mma_kernel<<<NCTA, NT, SMEMSZ>>>(x, bt, bfi, bg, al, nm, out);
}